// round 9
// baseline (speedup 1.0000x reference)
#include <cuda_runtime.h>
#include <cuda_bf16.h>
#include <cstdint>

#define N_WG   512
#define MPAIR  256
#define NCOL   512
#define N_NODE (NCOL * MPAIR)
#define BATCH  8192

// ===========================================================================
// Packed f32x2 helpers
// ===========================================================================
typedef unsigned long long F2;
__device__ __forceinline__ F2 pk(float lo, float hi) {
    F2 r; asm("mov.b64 %0, {%1, %2};" : "=l"(r) : "f"(lo), "f"(hi)); return r;
}
__device__ __forceinline__ void un2(F2 v, float& lo, float& hi) {
    asm("mov.b64 {%0, %1}, %2;" : "=f"(lo), "=f"(hi) : "l"(v));
}
__device__ __forceinline__ F2 splat(float a) { return pk(a, a); }
__device__ __forceinline__ F2 fma2(F2 a, F2 b, F2 c) {
    F2 d; asm("fma.rn.f32x2 %0, %1, %2, %3;" : "=l"(d) : "l"(a), "l"(b), "l"(c)); return d;
}
__device__ __forceinline__ F2 mul2(F2 a, F2 b) {
    F2 d; asm("mul.rn.f32x2 %0, %1, %2;" : "=l"(d) : "l"(a), "l"(b)); return d;
}
__device__ __forceinline__ float2 cmul(float2 a, float2 b) {
    return make_float2(a.x * b.x - a.y * b.y, a.x * b.y + a.y * b.x);
}
__device__ __forceinline__ float2 cadd(float2 a, float2 b) {
    return make_float2(a.x + b.x, a.y + b.y);
}
__device__ __forceinline__ uint32_t smem_u32(const void* p) {
    uint32_t a;
    asm("{ .reg .u64 t; cvta.to.shared.u64 t, %1; cvt.u32.u64 %0, t; }" : "=r"(a) : "l"(p));
    return a;
}

// ===========================================================================
// Static scratch
// ===========================================================================
// Packed per-node U: [2*idx]   = (u00.re, u00.im, u01.re, u01.im)
//                    [2*idx+1] = (u10.re, u10.im, u11.re, u11.im)
__device__ __align__(16) float4 g_Upk[N_NODE * 2];
__device__ __align__(16) __nv_bfloat16 g_Gh[1024 * 512];
__device__ __align__(16) __nv_bfloat16 g_Gl[1024 * 512];
__device__ __align__(16) __nv_bfloat16 g_Xh[512 * 8192];
__device__ __align__(16) __nv_bfloat16 g_Xl[512 * 8192];

// ===========================================================================
// Kernel 1 (fused): blocks [0,4096) convert X fp32->bf16 hi/lo;
//                   blocks [4096,4608) build per-node 2x2 U (packed).
// ===========================================================================
__global__ __launch_bounds__(256) void prep_kernel(
        const float4* __restrict__ X4,
        const float* __restrict__ th, const float* __restrict__ ph,
        const float* __restrict__ bse, const float* __restrict__ lse) {
    if (blockIdx.x < 4096) {
        int i = blockIdx.x * 256 + threadIdx.x;
        float4 v = X4[i];
        __nv_bfloat162 h0, h1, l0, l1;
        h0.x = __float2bfloat16(v.x); h0.y = __float2bfloat16(v.y);
        h1.x = __float2bfloat16(v.z); h1.y = __float2bfloat16(v.w);
        l0.x = __float2bfloat16(v.x - __bfloat162float(h0.x));
        l0.y = __float2bfloat16(v.y - __bfloat162float(h0.y));
        l1.x = __float2bfloat16(v.z - __bfloat162float(h1.x));
        l1.y = __float2bfloat16(v.w - __bfloat162float(h1.y));
        __nv_bfloat162* Xh2 = reinterpret_cast<__nv_bfloat162*>(g_Xh);
        __nv_bfloat162* Xl2 = reinterpret_cast<__nv_bfloat162*>(g_Xl);
        Xh2[2 * i] = h0; Xh2[2 * i + 1] = h1;
        Xl2[2 * i] = l0; Xl2[2 * i + 1] = l1;
        return;
    }
    int idx = (blockIdx.x - 4096) * 256 + threadIdx.x;
    int c = idx >> 8;
    int p = idx & 255;
    bool msk = ((c & 1) == 0) || (p < MPAIR - 1);

    float2 U00 = {1.f, 0.f}, U01 = {0.f, 0.f}, U10 = {0.f, 0.f}, U11 = {1.f, 0.f};
    if (msk) {
        float theta = th[idx], phi = ph[idx];
        float e0 = bse[2 * idx], e1 = bse[2 * idx + 1];
        float l0 = lse[2 * idx], l1 = lse[2 * idx + 1];
        const float KL = 0.11512925464970229f;  // ln(10)/20
        float ins0 = expf(l0 * KL), ins1 = expf(l1 * KL);
        const float PI4 = 0.7853981633974483f;
        float s0, c0, s1, c1;
        sincosf(PI4 + e0, &s0, &c0);
        sincosf(PI4 + e1, &s1, &c1);
        float2 EL, ET;
        sincosf(phi, &EL.y, &EL.x);
        sincosf(theta, &ET.y, &ET.x);
        float2 L11 = {ins0 * s0, 0.f}, L12 = {0.f, ins0 * c0}, L21 = {0.f, c0}, L22 = {s0, 0.f};
        float2 R11 = {ins1 * s1, 0.f}, R12 = {0.f, ins1 * c1}, R21 = {0.f, c1}, R22 = {s1, 0.f};
        float2 M00 = cmul(L11, cmul(EL, ET));
        float2 M10 = cmul(L12, EL);
        float2 M01 = cmul(L21, ET);
        float2 M11 = L22;
        U00 = cadd(cmul(R11, M00), cmul(R21, M10));
        U01 = cadd(cmul(R11, M01), cmul(R21, M11));
        U10 = cadd(cmul(R12, M00), cmul(R22, M10));
        U11 = cadd(cmul(R12, M01), cmul(R22, M11));
    }
    g_Upk[2 * idx]     = make_float4(U00.x, U00.y, U01.x, U01.y);
    g_Upk[2 * idx + 1] = make_float4(U10.x, U10.y, U11.x, U11.y);
}

// ===========================================================================
// Kernel 2: propagate identity*diag(e^{i gamma}) through mesh -> A (bf16 hi/lo).
// v5: ring of FOUR per-column smem U buffers, prefetch 3 ahead via cp.async.
// Tail fix: commit an EMPTY group when no real column remains, so the
// "wait_group 2 => column c resident" rank invariant holds for ALL c.
// ===========================================================================
__device__ __forceinline__ void apply2(const F2* S, F2& tr, F2& ti, F2& br, F2& bi) {
    F2 ntr = fma2(S[5],  bi, fma2(S[3], br, fma2(S[2], ti, mul2(S[0], tr))));
    F2 nti = fma2(S[4],  br, fma2(S[3], bi, fma2(S[1], tr, mul2(S[0], ti))));
    F2 nbr = fma2(S[11], bi, fma2(S[9], br, fma2(S[8], ti, mul2(S[6], tr))));
    F2 nbi = fma2(S[10], br, fma2(S[9], bi, fma2(S[7], tr, mul2(S[6], ti))));
    tr = ntr; ti = nti; br = nbr; bi = nbi;
}

__device__ __forceinline__ void store_split(int row, int col, float a, float b) {
    __nv_bfloat16 ha = __float2bfloat16(a), hb = __float2bfloat16(b);
    __nv_bfloat16 la = __float2bfloat16(a - __bfloat162float(ha));
    __nv_bfloat16 lb = __float2bfloat16(b - __bfloat162float(hb));
    __nv_bfloat162 h; h.x = ha; h.y = hb;
    __nv_bfloat162 l; l.x = la; l.y = lb;
    *reinterpret_cast<__nv_bfloat162*>(&g_Gh[(size_t)row * 512 + col]) = h;
    *reinterpret_cast<__nv_bfloat162*>(&g_Gl[(size_t)row * 512 + col]) = l;
}

__global__ __launch_bounds__(256) void build_A(const float* __restrict__ gammas) {
    int r  = threadIdx.x;
    int jb = blockIdx.x * 4;
    int i0 = 2 * r, i1 = 2 * r + 1;
    int lane = r & 31, w = r >> 5;

    float sg0, cg0, sg1, cg1;
    sincosf(gammas[i0], &sg0, &cg0);
    sincosf(gammas[i1], &sg1, &cg1);

    F2 are[2], aim[2], bre[2], bim[2];
#pragma unroll
    for (int k = 0; k < 2; k++) {
        int j0 = jb + 2 * k, j1 = j0 + 1;
        are[k] = pk(i0 == j0 ? cg0 : 0.f, i0 == j1 ? cg0 : 0.f);
        aim[k] = pk(i0 == j0 ? sg0 : 0.f, i0 == j1 ? sg0 : 0.f);
        bre[k] = pk(i1 == j0 ? cg1 : 0.f, i1 == j1 ? cg1 : 0.f);
        bim[k] = pk(i1 == j0 ? sg1 : 0.f, i1 == j1 ? sg1 : 0.f);
    }

    __shared__ F2 sEA[8][4];
    __shared__ F2 sEB[8][4];
    // 4-deep ring of per-column U buffers; thread r touches only slot r.
    __shared__ __align__(16) float4 sU0[4][256];
    __shared__ __align__(16) float4 sU1[4][256];

    auto issueC = [&](int c) {
        int buf = c & 3;
        const float4* s = g_Upk + ((size_t)(c << 8) + r) * 2;
        uint32_t d0 = smem_u32(&sU0[buf][r]);
        uint32_t d1 = smem_u32(&sU1[buf][r]);
        asm volatile("cp.async.cg.shared.global [%0], [%1], 16;" :: "r"(d0), "l"(s));
        asm volatile("cp.async.cg.shared.global [%0], [%1], 16;" :: "r"(d1), "l"(s + 1));
        asm volatile("cp.async.commit_group;" ::: "memory");
    };

    issueC(0); issueC(1); issueC(2);

    for (int c = 0; c < NCOL; c++) {
        asm volatile("cp.async.wait_group 2;" ::: "memory");   // column c resident
        int buf = c & 3;
        float4 u0 = sU0[buf][r];
        float4 u1 = sU1[buf][r];
        asm volatile("" ::: "memory");   // pin the reads before any new cp.async
        if (c + 3 < NCOL) {
            issueC(c + 3);
        } else {
            // keep one commit per iteration: empty group completes immediately,
            // preserving the rank invariant for the tail columns.
            asm volatile("cp.async.commit_group;" ::: "memory");
        }

        F2 S[12] = {
            splat(u0.x), splat(u0.y), splat(-u0.y),
            splat(u0.z), splat(u0.w), splat(-u0.w),
            splat(u1.x), splat(u1.y), splat(-u1.y),
            splat(u1.z), splat(u1.w), splat(-u1.w)
        };
        if ((c & 1) == 0) {
#pragma unroll
            for (int k = 0; k < 2; k++)
                apply2(S, are[k], aim[k], bre[k], bim[k]);
        } else {
            // pair p=r couples (row 2r+1 = my b, row 2r+2 = neighbor's a)
            F2 nar[2], nai[2];
#pragma unroll
            for (int k = 0; k < 2; k++) {
                nar[k] = __shfl_down_sync(0xffffffffu, are[k], 1);
                nai[k] = __shfl_down_sync(0xffffffffu, aim[k], 1);
            }
            if (lane == 0 && r > 0) {
                sEA[w][0] = are[0]; sEA[w][1] = are[1];
                sEA[w][2] = aim[0]; sEA[w][3] = aim[1];
            }
            __syncthreads();
            if (lane == 31 && r < 255) {
                nar[0] = sEA[w + 1][0]; nar[1] = sEA[w + 1][1];
                nai[0] = sEA[w + 1][2]; nai[1] = sEA[w + 1][3];
            }
            if (r < 255) {
#pragma unroll
                for (int k = 0; k < 2; k++)
                    apply2(S, bre[k], bim[k], nar[k], nai[k]);
            }
            // return updated bottom row (2r+2) to thread r+1's 'a'
            F2 up0 = __shfl_up_sync(0xffffffffu, nar[0], 1);
            F2 up1 = __shfl_up_sync(0xffffffffu, nar[1], 1);
            F2 up2 = __shfl_up_sync(0xffffffffu, nai[0], 1);
            F2 up3 = __shfl_up_sync(0xffffffffu, nai[1], 1);
            if (lane == 31 && r < 255) {
                sEB[w + 1][0] = nar[0]; sEB[w + 1][1] = nar[1];
                sEB[w + 1][2] = nai[0]; sEB[w + 1][3] = nai[1];
            }
            __syncthreads();
            if (r > 0) {
                if (lane == 0) {
                    are[0] = sEB[w][0]; are[1] = sEB[w][1];
                    aim[0] = sEB[w][2]; aim[1] = sEB[w][3];
                } else {
                    are[0] = up0; are[1] = up1; aim[0] = up2; aim[1] = up3;
                }
            }
        }
    }

    // emit bf16 hi/lo, m-major: rows [0,512)=Re, [512,1024)=Im
#pragma unroll
    for (int k = 0; k < 2; k++) {
        int j0 = jb + 2 * k;
        float x, y;
        un2(are[k], x, y); store_split(i0,       j0, x, y);
        un2(aim[k], x, y); store_split(512 + i0, j0, x, y);
        un2(bre[k], x, y); store_split(i1,       j0, x, y);
        un2(bim[k], x, y); store_split(512 + i1, j0, x, y);
    }
}

// ===========================================================================
// Kernel 3: mma.sync bf16 GEMM. out = Gh@Xh + Gh@Xl + Gl@Xh (fp32 accum).
// CTA 128x128, BK=32, 3-stage cp.async pipeline, 8 warps (32x64 each).
// ===========================================================================
__device__ __forceinline__ void ldmx4(uint32_t* r, uint32_t addr) {
    asm volatile("ldmatrix.sync.aligned.m8n8.x4.shared.b16 {%0,%1,%2,%3}, [%4];"
                 : "=r"(r[0]), "=r"(r[1]), "=r"(r[2]), "=r"(r[3]) : "r"(addr));
}
__device__ __forceinline__ void ldmx4t(uint32_t* r, uint32_t addr) {
    asm volatile("ldmatrix.sync.aligned.m8n8.x4.trans.shared.b16 {%0,%1,%2,%3}, [%4];"
                 : "=r"(r[0]), "=r"(r[1]), "=r"(r[2]), "=r"(r[3]) : "r"(addr));
}
__device__ __forceinline__ void mma_bf16(float* c, const uint32_t* a, uint32_t b0, uint32_t b1) {
    asm volatile("mma.sync.aligned.m16n8k16.row.col.f32.bf16.bf16.f32 "
                 "{%0,%1,%2,%3}, {%4,%5,%6,%7}, {%8,%9}, {%0,%1,%2,%3};"
                 : "+f"(c[0]), "+f"(c[1]), "+f"(c[2]), "+f"(c[3])
                 : "r"(a[0]), "r"(a[1]), "r"(a[2]), "r"(a[3]), "r"(b0), "r"(b1));
}

__global__ __launch_bounds__(256, 2) void mma_gemm(float* __restrict__ out) {
    __shared__ __align__(1024) char raw[3 * 16384];
    uint32_t sbase = smem_u32(raw);

    int tid = threadIdx.x;
    int lane = tid & 31, wid = tid >> 5;
    int wm = wid & 3, wn = wid >> 2;
    int bm = blockIdx.y * 128, bn = blockIdx.x * 128;

    auto issue = [&](int st, int buf) {
        int p = st >> 4;
        int kblk = (st & 15) << 5;
        const __nv_bfloat16* Ap = (p == 2) ? g_Gl : g_Gh;
        const __nv_bfloat16* Bp = (p == 1) ? g_Xl : g_Xh;
        uint32_t base = sbase + buf * 16384;
#pragma unroll
        for (int h = 0; h < 2; h++) {
            int cA = tid + h * 256;
            int row = cA >> 2, kc = cA & 3;
            uint32_t dA = base + row * 64 + ((kc ^ ((row >> 1) & 3)) << 4);
            const __nv_bfloat16* sA = Ap + (size_t)(bm + row) * 512 + kblk + kc * 8;
            asm volatile("cp.async.cg.shared.global [%0], [%1], 16;" :: "r"(dA), "l"(sA));
            int cB = tid + h * 256;
            int k = cB >> 4, nch = cB & 15;
            uint32_t dB = base + 8192 + k * 256 + ((nch ^ (k & 7)) << 4);
            const __nv_bfloat16* sB = Bp + (size_t)(kblk + k) * 8192 + bn + nch * 8;
            asm volatile("cp.async.cg.shared.global [%0], [%1], 16;" :: "r"(dB), "l"(sB));
        }
        asm volatile("cp.async.commit_group;" ::: "memory");
    };

    int grp = lane >> 3, lrow = lane & 7;
    int g1 = grp & 1, g2 = grp >> 1;
    int arow = wm * 32 + g1 * 8 + lrow;
    uint32_t aBase = arow * 64 + ((g2 ^ (lrow >> 1)) << 4);
    int bk = g1 * 8 + lrow;
    uint32_t bBase = 8192 + bk * 256 + wn * 128 + ((g2 ^ lrow) << 4);

    float acc[2][8][4];
#pragma unroll
    for (int mt = 0; mt < 2; mt++)
#pragma unroll
        for (int nj = 0; nj < 8; nj++)
#pragma unroll
            for (int q = 0; q < 4; q++) acc[mt][nj][q] = 0.f;

    issue(0, 0);
    issue(1, 1);

#pragma unroll 1
    for (int st = 0; st < 48; st++) {
        int buf = st % 3;
        if (st < 47) asm volatile("cp.async.wait_group 1;" ::: "memory");
        else         asm volatile("cp.async.wait_group 0;" ::: "memory");
        __syncthreads();
        if (st + 2 < 48) issue(st + 2, (st + 2) % 3);

        uint32_t stage = sbase + buf * 16384;
#pragma unroll
        for (int s = 0; s < 2; s++) {
            uint32_t a[2][4];
            ldmx4(a[0], (stage + aBase) ^ (s << 5));
            ldmx4(a[1], (stage + aBase + 16 * 64) ^ (s << 5));
#pragma unroll
            for (int j2 = 0; j2 < 4; j2++) {
                uint32_t b[4];
                ldmx4t(b, (stage + bBase + (s << 12)) ^ (j2 << 5));
#pragma unroll
                for (int mt = 0; mt < 2; mt++) {
                    mma_bf16(acc[mt][2 * j2],     a[mt], b[0], b[1]);
                    mma_bf16(acc[mt][2 * j2 + 1], a[mt], b[2], b[3]);
                }
            }
        }
    }

    int mrow = bm + wm * 32 + (lane >> 2);
    int ncol = bn + wn * 64 + (lane & 3) * 2;
#pragma unroll
    for (int mt = 0; mt < 2; mt++) {
#pragma unroll
        for (int nj = 0; nj < 8; nj++) {
            float* o = out + (size_t)(mrow + mt * 16) * 8192 + ncol + nj * 8;
            *reinterpret_cast<float2*>(o)             = make_float2(acc[mt][nj][0], acc[mt][nj][1]);
            *reinterpret_cast<float2*>(o + 8 * 8192)  = make_float2(acc[mt][nj][2], acc[mt][nj][3]);
        }
    }
}

// ===========================================================================
// Launch
// ===========================================================================
extern "C" void kernel_launch(void* const* d_in, const int* in_sizes, int n_in,
                              void* d_out, int out_size) {
    const float* x      = (const float*)d_in[0];
    const float* thetas = (const float*)d_in[1];
    const float* phis   = (const float*)d_in[2];
    const float* gammas = (const float*)d_in[3];
    const float* bse    = (const float*)d_in[4];
    const float* lse    = (const float*)d_in[5];
    (void)in_sizes; (void)n_in; (void)out_size;

    prep_kernel<<<4096 + 512, 256>>>((const float4*)x, thetas, phis, bse, lse);
    build_A<<<128, 256>>>(gammas);
    mma_gemm<<<dim3(64, 8), 256>>>((float*)d_out);
}

// round 10
// speedup vs baseline: 1.3566x; 1.3566x over previous
#include <cuda_runtime.h>
#include <cuda_bf16.h>
#include <cstdint>

#define N_WG   512
#define MPAIR  256
#define NCOL   512
#define N_NODE (NCOL * MPAIR)
#define BATCH  8192

// ===========================================================================
// Packed f32x2 helpers
// ===========================================================================
typedef unsigned long long F2;
__device__ __forceinline__ F2 pk(float lo, float hi) {
    F2 r; asm("mov.b64 %0, {%1, %2};" : "=l"(r) : "f"(lo), "f"(hi)); return r;
}
__device__ __forceinline__ void un2(F2 v, float& lo, float& hi) {
    asm("mov.b64 {%0, %1}, %2;" : "=f"(lo), "=f"(hi) : "l"(v));
}
__device__ __forceinline__ F2 splat(float a) { return pk(a, a); }
__device__ __forceinline__ F2 fma2(F2 a, F2 b, F2 c) {
    F2 d; asm("fma.rn.f32x2 %0, %1, %2, %3;" : "=l"(d) : "l"(a), "l"(b), "l"(c)); return d;
}
__device__ __forceinline__ F2 mul2(F2 a, F2 b) {
    F2 d; asm("mul.rn.f32x2 %0, %1, %2;" : "=l"(d) : "l"(a), "l"(b)); return d;
}
__device__ __forceinline__ float2 cmul(float2 a, float2 b) {
    return make_float2(a.x * b.x - a.y * b.y, a.x * b.y + a.y * b.x);
}
__device__ __forceinline__ float2 cadd(float2 a, float2 b) {
    return make_float2(a.x + b.x, a.y + b.y);
}
__device__ __forceinline__ uint32_t smem_u32(const void* p) {
    uint32_t a;
    asm("{ .reg .u64 t; cvta.to.shared.u64 t, %1; cvt.u32.u64 %0, t; }" : "=r"(a) : "l"(p));
    return a;
}

// ===========================================================================
// Static scratch
// ===========================================================================
__device__ float2 g_U00[N_NODE], g_U01[N_NODE], g_U10[N_NODE], g_U11[N_NODE];
__device__ __align__(16) __nv_bfloat16 g_Gh[1024 * 512];
__device__ __align__(16) __nv_bfloat16 g_Gl[1024 * 512];
__device__ __align__(16) __nv_bfloat16 g_Xh[512 * 8192];
__device__ __align__(16) __nv_bfloat16 g_Xl[512 * 8192];

// ===========================================================================
// Kernel 1 (fused): blocks [0,4096) convert X fp32->bf16 hi/lo;
//                   blocks [4096,4608) build per-node 2x2 U.
// ===========================================================================
__global__ __launch_bounds__(256) void prep_kernel(
        const float4* __restrict__ X4,
        const float* __restrict__ th, const float* __restrict__ ph,
        const float* __restrict__ bse, const float* __restrict__ lse) {
    if (blockIdx.x < 4096) {
        int i = blockIdx.x * 256 + threadIdx.x;
        float4 v = X4[i];
        __nv_bfloat162 h0, h1, l0, l1;
        h0.x = __float2bfloat16(v.x); h0.y = __float2bfloat16(v.y);
        h1.x = __float2bfloat16(v.z); h1.y = __float2bfloat16(v.w);
        l0.x = __float2bfloat16(v.x - __bfloat162float(h0.x));
        l0.y = __float2bfloat16(v.y - __bfloat162float(h0.y));
        l1.x = __float2bfloat16(v.z - __bfloat162float(h1.x));
        l1.y = __float2bfloat16(v.w - __bfloat162float(h1.y));
        __nv_bfloat162* Xh2 = reinterpret_cast<__nv_bfloat162*>(g_Xh);
        __nv_bfloat162* Xl2 = reinterpret_cast<__nv_bfloat162*>(g_Xl);
        Xh2[2 * i] = h0; Xh2[2 * i + 1] = h1;
        Xl2[2 * i] = l0; Xl2[2 * i + 1] = l1;
        return;
    }
    int idx = (blockIdx.x - 4096) * 256 + threadIdx.x;
    int c = idx >> 8;
    int p = idx & 255;
    bool msk = ((c & 1) == 0) || (p < MPAIR - 1);

    float2 U00 = {1.f, 0.f}, U01 = {0.f, 0.f}, U10 = {0.f, 0.f}, U11 = {1.f, 0.f};
    if (msk) {
        float theta = th[idx], phi = ph[idx];
        float e0 = bse[2 * idx], e1 = bse[2 * idx + 1];
        float l0 = lse[2 * idx], l1 = lse[2 * idx + 1];
        const float KL = 0.11512925464970229f;  // ln(10)/20
        float ins0 = expf(l0 * KL), ins1 = expf(l1 * KL);
        const float PI4 = 0.7853981633974483f;
        float s0, c0, s1, c1;
        sincosf(PI4 + e0, &s0, &c0);
        sincosf(PI4 + e1, &s1, &c1);
        float2 EL, ET;
        sincosf(phi, &EL.y, &EL.x);
        sincosf(theta, &ET.y, &ET.x);
        float2 L11 = {ins0 * s0, 0.f}, L12 = {0.f, ins0 * c0}, L21 = {0.f, c0}, L22 = {s0, 0.f};
        float2 R11 = {ins1 * s1, 0.f}, R12 = {0.f, ins1 * c1}, R21 = {0.f, c1}, R22 = {s1, 0.f};
        float2 M00 = cmul(L11, cmul(EL, ET));
        float2 M10 = cmul(L12, EL);
        float2 M01 = cmul(L21, ET);
        float2 M11 = L22;
        U00 = cadd(cmul(R11, M00), cmul(R21, M10));
        U01 = cadd(cmul(R11, M01), cmul(R21, M11));
        U10 = cadd(cmul(R12, M00), cmul(R22, M10));
        U11 = cadd(cmul(R12, M01), cmul(R22, M11));
    }
    g_U00[idx] = U00; g_U01[idx] = U01; g_U10[idx] = U10; g_U11[idx] = U11;
}

// ===========================================================================
// Kernel 2: propagate identity*diag(e^{i gamma}) through mesh -> A (bf16 hi/lo).
// v6: round-3 structure VERBATIM but 2 A-columns per thread (half state) and
// 256 CTAs -> 2 CTAs/SM. The second CTA's compute fills the first CTA's
// shfl/barrier latency holes.
// ===========================================================================
__device__ __forceinline__ void apply2(const F2* S, F2& tr, F2& ti, F2& br, F2& bi) {
    F2 ntr = fma2(S[5],  bi, fma2(S[3], br, fma2(S[2], ti, mul2(S[0], tr))));
    F2 nti = fma2(S[4],  br, fma2(S[3], bi, fma2(S[1], tr, mul2(S[0], ti))));
    F2 nbr = fma2(S[11], bi, fma2(S[9], br, fma2(S[8], ti, mul2(S[6], tr))));
    F2 nbi = fma2(S[10], br, fma2(S[9], bi, fma2(S[7], tr, mul2(S[6], ti))));
    tr = ntr; ti = nti; br = nbr; bi = nbi;
}

__device__ __forceinline__ void store_split(int row, int col, float a, float b) {
    __nv_bfloat16 ha = __float2bfloat16(a), hb = __float2bfloat16(b);
    __nv_bfloat16 la = __float2bfloat16(a - __bfloat162float(ha));
    __nv_bfloat16 lb = __float2bfloat16(b - __bfloat162float(hb));
    __nv_bfloat162 h; h.x = ha; h.y = hb;
    __nv_bfloat162 l; l.x = la; l.y = lb;
    *reinterpret_cast<__nv_bfloat162*>(&g_Gh[(size_t)row * 512 + col]) = h;
    *reinterpret_cast<__nv_bfloat162*>(&g_Gl[(size_t)row * 512 + col]) = l;
}

__global__ __launch_bounds__(256, 2) void build_A(const float* __restrict__ gammas) {
    int r  = threadIdx.x;
    int jb = blockIdx.x * 2;           // 2 A-columns per CTA
    int i0 = 2 * r, i1 = 2 * r + 1;
    int lane = r & 31, w = r >> 5;

    float sg0, cg0, sg1, cg1;
    sincosf(gammas[i0], &sg0, &cg0);
    sincosf(gammas[i1], &sg1, &cg1);

    int j0 = jb, j1 = jb + 1;
    F2 are = pk(i0 == j0 ? cg0 : 0.f, i0 == j1 ? cg0 : 0.f);
    F2 aim = pk(i0 == j0 ? sg0 : 0.f, i0 == j1 ? sg0 : 0.f);
    F2 bre = pk(i1 == j0 ? cg1 : 0.f, i1 == j1 ? cg1 : 0.f);
    F2 bim = pk(i1 == j0 ? sg1 : 0.f, i1 == j1 ? sg1 : 0.f);

    __shared__ F2 sEA[8][2];
    __shared__ F2 sEB[8][2];

    // prefetch column 0 coefficients
    float2 u00 = g_U00[r], u01 = g_U01[r], u10 = g_U10[r], u11 = g_U11[r];

    for (int c = 0; c < NCOL; c++) {
        // prefetch next column's U while computing this one
        float2 p00, p01, p10, p11;
        if (c + 1 < NCOL) {
            int nidx = ((c + 1) << 8) + r;
            p00 = g_U00[nidx]; p01 = g_U01[nidx]; p10 = g_U10[nidx]; p11 = g_U11[nidx];
        }
        F2 S[12] = {
            splat(u00.x), splat(u00.y), splat(-u00.y),
            splat(u01.x), splat(u01.y), splat(-u01.y),
            splat(u10.x), splat(u10.y), splat(-u10.y),
            splat(u11.x), splat(u11.y), splat(-u11.y)
        };
        if ((c & 1) == 0) {
            apply2(S, are, aim, bre, bim);
        } else {
            // pair p=r couples (row 2r+1 = my b, row 2r+2 = neighbor's a)
            F2 nar = __shfl_down_sync(0xffffffffu, are, 1);
            F2 nai = __shfl_down_sync(0xffffffffu, aim, 1);
            if (lane == 0 && r > 0) {
                sEA[w][0] = are; sEA[w][1] = aim;
            }
            __syncthreads();
            if (lane == 31 && r < 255) {
                nar = sEA[w + 1][0]; nai = sEA[w + 1][1];
            }
            if (r < 255) {
                apply2(S, bre, bim, nar, nai);
            }
            // return updated bottom row (2r+2) to thread r+1's 'a'
            F2 up0 = __shfl_up_sync(0xffffffffu, nar, 1);
            F2 up1 = __shfl_up_sync(0xffffffffu, nai, 1);
            if (lane == 31 && r < 255) {
                sEB[w + 1][0] = nar; sEB[w + 1][1] = nai;
            }
            __syncthreads();
            if (r > 0) {
                if (lane == 0) {
                    are = sEB[w][0]; aim = sEB[w][1];
                } else {
                    are = up0; aim = up1;
                }
            }
        }
        u00 = p00; u01 = p01; u10 = p10; u11 = p11;
    }

    // emit bf16 hi/lo, m-major: rows [0,512)=Re, [512,1024)=Im
    {
        float x, y;
        un2(are, x, y); store_split(i0,       jb, x, y);
        un2(aim, x, y); store_split(512 + i0, jb, x, y);
        un2(bre, x, y); store_split(i1,       jb, x, y);
        un2(bim, x, y); store_split(512 + i1, jb, x, y);
    }
}

// ===========================================================================
// Kernel 3: mma.sync bf16 GEMM. out = Gh@Xh + Gh@Xl + Gl@Xh (fp32 accum).
// CTA 128x128, BK=32, 3-stage cp.async pipeline, 8 warps (32x64 each).
// ===========================================================================
__device__ __forceinline__ void ldmx4(uint32_t* r, uint32_t addr) {
    asm volatile("ldmatrix.sync.aligned.m8n8.x4.shared.b16 {%0,%1,%2,%3}, [%4];"
                 : "=r"(r[0]), "=r"(r[1]), "=r"(r[2]), "=r"(r[3]) : "r"(addr));
}
__device__ __forceinline__ void ldmx4t(uint32_t* r, uint32_t addr) {
    asm volatile("ldmatrix.sync.aligned.m8n8.x4.trans.shared.b16 {%0,%1,%2,%3}, [%4];"
                 : "=r"(r[0]), "=r"(r[1]), "=r"(r[2]), "=r"(r[3]) : "r"(addr));
}
__device__ __forceinline__ void mma_bf16(float* c, const uint32_t* a, uint32_t b0, uint32_t b1) {
    asm volatile("mma.sync.aligned.m16n8k16.row.col.f32.bf16.bf16.f32 "
                 "{%0,%1,%2,%3}, {%4,%5,%6,%7}, {%8,%9}, {%0,%1,%2,%3};"
                 : "+f"(c[0]), "+f"(c[1]), "+f"(c[2]), "+f"(c[3])
                 : "r"(a[0]), "r"(a[1]), "r"(a[2]), "r"(a[3]), "r"(b0), "r"(b1));
}

__global__ __launch_bounds__(256, 2) void mma_gemm(float* __restrict__ out) {
    __shared__ __align__(1024) char raw[3 * 16384];
    uint32_t sbase = smem_u32(raw);

    int tid = threadIdx.x;
    int lane = tid & 31, wid = tid >> 5;
    int wm = wid & 3, wn = wid >> 2;
    int bm = blockIdx.y * 128, bn = blockIdx.x * 128;

    auto issue = [&](int st, int buf) {
        int p = st >> 4;
        int kblk = (st & 15) << 5;
        const __nv_bfloat16* Ap = (p == 2) ? g_Gl : g_Gh;
        const __nv_bfloat16* Bp = (p == 1) ? g_Xl : g_Xh;
        uint32_t base = sbase + buf * 16384;
#pragma unroll
        for (int h = 0; h < 2; h++) {
            int cA = tid + h * 256;
            int row = cA >> 2, kc = cA & 3;
            uint32_t dA = base + row * 64 + ((kc ^ ((row >> 1) & 3)) << 4);
            const __nv_bfloat16* sA = Ap + (size_t)(bm + row) * 512 + kblk + kc * 8;
            asm volatile("cp.async.cg.shared.global [%0], [%1], 16;" :: "r"(dA), "l"(sA));
            int cB = tid + h * 256;
            int k = cB >> 4, nch = cB & 15;
            uint32_t dB = base + 8192 + k * 256 + ((nch ^ (k & 7)) << 4);
            const __nv_bfloat16* sB = Bp + (size_t)(kblk + k) * 8192 + bn + nch * 8;
            asm volatile("cp.async.cg.shared.global [%0], [%1], 16;" :: "r"(dB), "l"(sB));
        }
        asm volatile("cp.async.commit_group;" ::: "memory");
    };

    int grp = lane >> 3, lrow = lane & 7;
    int g1 = grp & 1, g2 = grp >> 1;
    int arow = wm * 32 + g1 * 8 + lrow;
    uint32_t aBase = arow * 64 + ((g2 ^ (lrow >> 1)) << 4);
    int bk = g1 * 8 + lrow;
    uint32_t bBase = 8192 + bk * 256 + wn * 128 + ((g2 ^ lrow) << 4);

    float acc[2][8][4];
#pragma unroll
    for (int mt = 0; mt < 2; mt++)
#pragma unroll
        for (int nj = 0; nj < 8; nj++)
#pragma unroll
            for (int q = 0; q < 4; q++) acc[mt][nj][q] = 0.f;

    issue(0, 0);
    issue(1, 1);

#pragma unroll 1
    for (int st = 0; st < 48; st++) {
        int buf = st % 3;
        if (st < 47) asm volatile("cp.async.wait_group 1;" ::: "memory");
        else         asm volatile("cp.async.wait_group 0;" ::: "memory");
        __syncthreads();
        if (st + 2 < 48) issue(st + 2, (st + 2) % 3);

        uint32_t stage = sbase + buf * 16384;
#pragma unroll
        for (int s = 0; s < 2; s++) {
            uint32_t a[2][4];
            ldmx4(a[0], (stage + aBase) ^ (s << 5));
            ldmx4(a[1], (stage + aBase + 16 * 64) ^ (s << 5));
#pragma unroll
            for (int j2 = 0; j2 < 4; j2++) {
                uint32_t b[4];
                ldmx4t(b, (stage + bBase + (s << 12)) ^ (j2 << 5));
#pragma unroll
                for (int mt = 0; mt < 2; mt++) {
                    mma_bf16(acc[mt][2 * j2],     a[mt], b[0], b[1]);
                    mma_bf16(acc[mt][2 * j2 + 1], a[mt], b[2], b[3]);
                }
            }
        }
    }

    int mrow = bm + wm * 32 + (lane >> 2);
    int ncol = bn + wn * 64 + (lane & 3) * 2;
#pragma unroll
    for (int mt = 0; mt < 2; mt++) {
#pragma unroll
        for (int nj = 0; nj < 8; nj++) {
            float* o = out + (size_t)(mrow + mt * 16) * 8192 + ncol + nj * 8;
            *reinterpret_cast<float2*>(o)             = make_float2(acc[mt][nj][0], acc[mt][nj][1]);
            *reinterpret_cast<float2*>(o + 8 * 8192)  = make_float2(acc[mt][nj][2], acc[mt][nj][3]);
        }
    }
}

// ===========================================================================
// Launch
// ===========================================================================
extern "C" void kernel_launch(void* const* d_in, const int* in_sizes, int n_in,
                              void* d_out, int out_size) {
    const float* x      = (const float*)d_in[0];
    const float* thetas = (const float*)d_in[1];
    const float* phis   = (const float*)d_in[2];
    const float* gammas = (const float*)d_in[3];
    const float* bse    = (const float*)d_in[4];
    const float* lse    = (const float*)d_in[5];
    (void)in_sizes; (void)n_in; (void)out_size;

    prep_kernel<<<4096 + 512, 256>>>((const float4*)x, thetas, phis, bse, lse);
    build_A<<<256, 256>>>(gammas);
    mma_gemm<<<dim3(64, 8), 256>>>((float*)d_out);
}

// round 11
// speedup vs baseline: 1.8599x; 1.3710x over previous
#include <cuda_runtime.h>
#include <cuda_fp16.h>
#include <cstdint>

#define N_WG   512
#define MPAIR  256
#define NCOL   512
#define N_NODE (NCOL * MPAIR)
#define BATCH  8192

// ===========================================================================
// Packed f32x2 helpers
// ===========================================================================
typedef unsigned long long F2;
__device__ __forceinline__ F2 pk(float lo, float hi) {
    F2 r; asm("mov.b64 %0, {%1, %2};" : "=l"(r) : "f"(lo), "f"(hi)); return r;
}
__device__ __forceinline__ void un2(F2 v, float& lo, float& hi) {
    asm("mov.b64 {%0, %1}, %2;" : "=f"(lo), "=f"(hi) : "l"(v));
}
__device__ __forceinline__ F2 splat(float a) { return pk(a, a); }
__device__ __forceinline__ F2 fma2(F2 a, F2 b, F2 c) {
    F2 d; asm("fma.rn.f32x2 %0, %1, %2, %3;" : "=l"(d) : "l"(a), "l"(b), "l"(c)); return d;
}
__device__ __forceinline__ F2 mul2(F2 a, F2 b) {
    F2 d; asm("mul.rn.f32x2 %0, %1, %2;" : "=l"(d) : "l"(a), "l"(b)); return d;
}
__device__ __forceinline__ float2 cmul(float2 a, float2 b) {
    return make_float2(a.x * b.x - a.y * b.y, a.x * b.y + a.y * b.x);
}
__device__ __forceinline__ float2 cadd(float2 a, float2 b) {
    return make_float2(a.x + b.x, a.y + b.y);
}
__device__ __forceinline__ uint32_t smem_u32(const void* p) {
    uint32_t a;
    asm("{ .reg .u64 t; cvta.to.shared.u64 t, %1; cvt.u32.u64 %0, t; }" : "=r"(a) : "l"(p));
    return a;
}

// ===========================================================================
// Static scratch
// ===========================================================================
__device__ float2 g_U00[N_NODE], g_U01[N_NODE], g_U10[N_NODE], g_U11[N_NODE];
// A matrix (rows 0-511 = Re, 512-1023 = Im), m-major, single fp16
__device__ __align__(16) __half g_G[1024 * 512];
// X, [k][n] layout, single fp16
__device__ __align__(16) __half g_X[512 * 8192];

// ===========================================================================
// Kernel 1 (fused): blocks [0,4096) convert X fp32->fp16;
//                   blocks [4096,4608) build per-node 2x2 U.
// ===========================================================================
__global__ __launch_bounds__(256) void prep_kernel(
        const float4* __restrict__ X4,
        const float* __restrict__ th, const float* __restrict__ ph,
        const float* __restrict__ bse, const float* __restrict__ lse) {
    if (blockIdx.x < 4096) {
        int i = blockIdx.x * 256 + threadIdx.x;
        float4 v = X4[i];
        __half2 h0, h1;
        h0.x = __float2half_rn(v.x); h0.y = __float2half_rn(v.y);
        h1.x = __float2half_rn(v.z); h1.y = __float2half_rn(v.w);
        __half2* X2 = reinterpret_cast<__half2*>(g_X);
        X2[2 * i] = h0; X2[2 * i + 1] = h1;
        return;
    }
    int idx = (blockIdx.x - 4096) * 256 + threadIdx.x;
    int c = idx >> 8;
    int p = idx & 255;
    bool msk = ((c & 1) == 0) || (p < MPAIR - 1);

    float2 U00 = {1.f, 0.f}, U01 = {0.f, 0.f}, U10 = {0.f, 0.f}, U11 = {1.f, 0.f};
    if (msk) {
        float theta = th[idx], phi = ph[idx];
        float e0 = bse[2 * idx], e1 = bse[2 * idx + 1];
        float l0 = lse[2 * idx], l1 = lse[2 * idx + 1];
        const float KL = 0.11512925464970229f;  // ln(10)/20
        float ins0 = expf(l0 * KL), ins1 = expf(l1 * KL);
        const float PI4 = 0.7853981633974483f;
        float s0, c0, s1, c1;
        sincosf(PI4 + e0, &s0, &c0);
        sincosf(PI4 + e1, &s1, &c1);
        float2 EL, ET;
        sincosf(phi, &EL.y, &EL.x);
        sincosf(theta, &ET.y, &ET.x);
        float2 L11 = {ins0 * s0, 0.f}, L12 = {0.f, ins0 * c0}, L21 = {0.f, c0}, L22 = {s0, 0.f};
        float2 R11 = {ins1 * s1, 0.f}, R12 = {0.f, ins1 * c1}, R21 = {0.f, c1}, R22 = {s1, 0.f};
        float2 M00 = cmul(L11, cmul(EL, ET));
        float2 M10 = cmul(L12, EL);
        float2 M01 = cmul(L21, ET);
        float2 M11 = L22;
        U00 = cadd(cmul(R11, M00), cmul(R21, M10));
        U01 = cadd(cmul(R11, M01), cmul(R21, M11));
        U10 = cadd(cmul(R12, M00), cmul(R22, M10));
        U11 = cadd(cmul(R12, M01), cmul(R22, M11));
    }
    g_U00[idx] = U00; g_U01[idx] = U01; g_U10[idx] = U10; g_U11[idx] = U11;
}

// ===========================================================================
// Kernel 2: propagate identity*diag(e^{i gamma}) through mesh -> A (fp16).
// Round-10 winning structure verbatim (2 j-cols/CTA, 256 CTAs, 2 CTAs/SM).
// ===========================================================================
__device__ __forceinline__ void apply2(const F2* S, F2& tr, F2& ti, F2& br, F2& bi) {
    F2 ntr = fma2(S[5],  bi, fma2(S[3], br, fma2(S[2], ti, mul2(S[0], tr))));
    F2 nti = fma2(S[4],  br, fma2(S[3], bi, fma2(S[1], tr, mul2(S[0], ti))));
    F2 nbr = fma2(S[11], bi, fma2(S[9], br, fma2(S[8], ti, mul2(S[6], tr))));
    F2 nbi = fma2(S[10], br, fma2(S[9], bi, fma2(S[7], tr, mul2(S[6], ti))));
    tr = ntr; ti = nti; br = nbr; bi = nbi;
}

__device__ __forceinline__ void store_h(int row, int col, float a, float b) {
    __half2 h;
    h.x = __float2half_rn(a);
    h.y = __float2half_rn(b);
    *reinterpret_cast<__half2*>(&g_G[(size_t)row * 512 + col]) = h;
}

__global__ __launch_bounds__(256, 2) void build_A(const float* __restrict__ gammas) {
    int r  = threadIdx.x;
    int jb = blockIdx.x * 2;           // 2 A-columns per CTA
    int i0 = 2 * r, i1 = 2 * r + 1;
    int lane = r & 31, w = r >> 5;

    float sg0, cg0, sg1, cg1;
    sincosf(gammas[i0], &sg0, &cg0);
    sincosf(gammas[i1], &sg1, &cg1);

    int j0 = jb, j1 = jb + 1;
    F2 are = pk(i0 == j0 ? cg0 : 0.f, i0 == j1 ? cg0 : 0.f);
    F2 aim = pk(i0 == j0 ? sg0 : 0.f, i0 == j1 ? sg0 : 0.f);
    F2 bre = pk(i1 == j0 ? cg1 : 0.f, i1 == j1 ? cg1 : 0.f);
    F2 bim = pk(i1 == j0 ? sg1 : 0.f, i1 == j1 ? sg1 : 0.f);

    __shared__ F2 sEA[8][2];
    __shared__ F2 sEB[8][2];

    // prefetch column 0 coefficients
    float2 u00 = g_U00[r], u01 = g_U01[r], u10 = g_U10[r], u11 = g_U11[r];

    for (int c = 0; c < NCOL; c++) {
        float2 p00, p01, p10, p11;
        if (c + 1 < NCOL) {
            int nidx = ((c + 1) << 8) + r;
            p00 = g_U00[nidx]; p01 = g_U01[nidx]; p10 = g_U10[nidx]; p11 = g_U11[nidx];
        }
        F2 S[12] = {
            splat(u00.x), splat(u00.y), splat(-u00.y),
            splat(u01.x), splat(u01.y), splat(-u01.y),
            splat(u10.x), splat(u10.y), splat(-u10.y),
            splat(u11.x), splat(u11.y), splat(-u11.y)
        };
        if ((c & 1) == 0) {
            apply2(S, are, aim, bre, bim);
        } else {
            // pair p=r couples (row 2r+1 = my b, row 2r+2 = neighbor's a)
            F2 nar = __shfl_down_sync(0xffffffffu, are, 1);
            F2 nai = __shfl_down_sync(0xffffffffu, aim, 1);
            if (lane == 0 && r > 0) {
                sEA[w][0] = are; sEA[w][1] = aim;
            }
            __syncthreads();
            if (lane == 31 && r < 255) {
                nar = sEA[w + 1][0]; nai = sEA[w + 1][1];
            }
            if (r < 255) {
                apply2(S, bre, bim, nar, nai);
            }
            F2 up0 = __shfl_up_sync(0xffffffffu, nar, 1);
            F2 up1 = __shfl_up_sync(0xffffffffu, nai, 1);
            if (lane == 31 && r < 255) {
                sEB[w + 1][0] = nar; sEB[w + 1][1] = nai;
            }
            __syncthreads();
            if (r > 0) {
                if (lane == 0) {
                    are = sEB[w][0]; aim = sEB[w][1];
                } else {
                    are = up0; aim = up1;
                }
            }
        }
        u00 = p00; u01 = p01; u10 = p10; u11 = p11;
    }

    // emit fp16, m-major: rows [0,512)=Re, [512,1024)=Im
    {
        float x, y;
        un2(are, x, y); store_h(i0,       jb, x, y);
        un2(aim, x, y); store_h(512 + i0, jb, x, y);
        un2(bre, x, y); store_h(i1,       jb, x, y);
        un2(bim, x, y); store_h(512 + i1, jb, x, y);
    }
}

// ===========================================================================
// Kernel 3: single-pass fp16 mma.sync GEMM. out[1024][8192] = G @ X (fp32 acc).
// CTA 128x128, BK=32, 3-stage cp.async pipeline, 8 warps (32x64 each).
// K = 512 -> 16 stages.
// ===========================================================================
__device__ __forceinline__ void ldmx4(uint32_t* r, uint32_t addr) {
    asm volatile("ldmatrix.sync.aligned.m8n8.x4.shared.b16 {%0,%1,%2,%3}, [%4];"
                 : "=r"(r[0]), "=r"(r[1]), "=r"(r[2]), "=r"(r[3]) : "r"(addr));
}
__device__ __forceinline__ void ldmx4t(uint32_t* r, uint32_t addr) {
    asm volatile("ldmatrix.sync.aligned.m8n8.x4.trans.shared.b16 {%0,%1,%2,%3}, [%4];"
                 : "=r"(r[0]), "=r"(r[1]), "=r"(r[2]), "=r"(r[3]) : "r"(addr));
}
__device__ __forceinline__ void mma_f16(float* c, const uint32_t* a, uint32_t b0, uint32_t b1) {
    asm volatile("mma.sync.aligned.m16n8k16.row.col.f32.f16.f16.f32 "
                 "{%0,%1,%2,%3}, {%4,%5,%6,%7}, {%8,%9}, {%0,%1,%2,%3};"
                 : "+f"(c[0]), "+f"(c[1]), "+f"(c[2]), "+f"(c[3])
                 : "r"(a[0]), "r"(a[1]), "r"(a[2]), "r"(a[3]), "r"(b0), "r"(b1));
}

__global__ __launch_bounds__(256, 2) void mma_gemm(float* __restrict__ out) {
    __shared__ __align__(1024) char raw[3 * 16384];
    uint32_t sbase = smem_u32(raw);

    int tid = threadIdx.x;
    int lane = tid & 31, wid = tid >> 5;
    int wm = wid & 3, wn = wid >> 2;
    int bm = blockIdx.y * 128, bn = blockIdx.x * 128;

    auto issue = [&](int st, int buf) {
        int kblk = st << 5;
        uint32_t base = sbase + buf * 16384;
#pragma unroll
        for (int h = 0; h < 2; h++) {
            int cA = tid + h * 256;
            int row = cA >> 2, kc = cA & 3;
            uint32_t dA = base + row * 64 + ((kc ^ ((row >> 1) & 3)) << 4);
            const __half* sA = g_G + (size_t)(bm + row) * 512 + kblk + kc * 8;
            asm volatile("cp.async.cg.shared.global [%0], [%1], 16;" :: "r"(dA), "l"(sA));
            int cB = tid + h * 256;
            int k = cB >> 4, nch = cB & 15;
            uint32_t dB = base + 8192 + k * 256 + ((nch ^ (k & 7)) << 4);
            const __half* sB = g_X + (size_t)(kblk + k) * 8192 + bn + nch * 8;
            asm volatile("cp.async.cg.shared.global [%0], [%1], 16;" :: "r"(dB), "l"(sB));
        }
        asm volatile("cp.async.commit_group;" ::: "memory");
    };

    int grp = lane >> 3, lrow = lane & 7;
    int g1 = grp & 1, g2 = grp >> 1;
    int arow = wm * 32 + g1 * 8 + lrow;
    uint32_t aBase = arow * 64 + ((g2 ^ (lrow >> 1)) << 4);
    int bk = g1 * 8 + lrow;
    uint32_t bBase = 8192 + bk * 256 + wn * 128 + ((g2 ^ lrow) << 4);

    float acc[2][8][4];
#pragma unroll
    for (int mt = 0; mt < 2; mt++)
#pragma unroll
        for (int nj = 0; nj < 8; nj++)
#pragma unroll
            for (int q = 0; q < 4; q++) acc[mt][nj][q] = 0.f;

    issue(0, 0);
    issue(1, 1);

#pragma unroll 1
    for (int st = 0; st < 16; st++) {
        int buf = st % 3;
        if (st < 15) asm volatile("cp.async.wait_group 1;" ::: "memory");
        else         asm volatile("cp.async.wait_group 0;" ::: "memory");
        __syncthreads();
        if (st + 2 < 16) issue(st + 2, (st + 2) % 3);

        uint32_t stage = sbase + buf * 16384;
#pragma unroll
        for (int s = 0; s < 2; s++) {
            uint32_t a[2][4];
            ldmx4(a[0], (stage + aBase) ^ (s << 5));
            ldmx4(a[1], (stage + aBase + 16 * 64) ^ (s << 5));
#pragma unroll
            for (int j2 = 0; j2 < 4; j2++) {
                uint32_t b[4];
                ldmx4t(b, (stage + bBase + (s << 12)) ^ (j2 << 5));
#pragma unroll
                for (int mt = 0; mt < 2; mt++) {
                    mma_f16(acc[mt][2 * j2],     a[mt], b[0], b[1]);
                    mma_f16(acc[mt][2 * j2 + 1], a[mt], b[2], b[3]);
                }
            }
        }
    }

    int mrow = bm + wm * 32 + (lane >> 2);
    int ncol = bn + wn * 64 + (lane & 3) * 2;
#pragma unroll
    for (int mt = 0; mt < 2; mt++) {
#pragma unroll
        for (int nj = 0; nj < 8; nj++) {
            float* o = out + (size_t)(mrow + mt * 16) * 8192 + ncol + nj * 8;
            *reinterpret_cast<float2*>(o)             = make_float2(acc[mt][nj][0], acc[mt][nj][1]);
            *reinterpret_cast<float2*>(o + 8 * 8192)  = make_float2(acc[mt][nj][2], acc[mt][nj][3]);
        }
    }
}

// ===========================================================================
// Launch
// ===========================================================================
extern "C" void kernel_launch(void* const* d_in, const int* in_sizes, int n_in,
                              void* d_out, int out_size) {
    const float* x      = (const float*)d_in[0];
    const float* thetas = (const float*)d_in[1];
    const float* phis   = (const float*)d_in[2];
    const float* gammas = (const float*)d_in[3];
    const float* bse    = (const float*)d_in[4];
    const float* lse    = (const float*)d_in[5];
    (void)in_sizes; (void)n_in; (void)out_size;

    prep_kernel<<<4096 + 512, 256>>>((const float4*)x, thetas, phis, bse, lse);
    build_A<<<256, 256>>>(gammas);
    mma_gemm<<<dim3(64, 8), 256>>>((float*)d_out);
}